// round 9
// baseline (speedup 1.0000x reference)
#include <cuda_runtime.h>
#include <cuda_fp16.h>
#include <cstdint>

#define N_NODES 50000
#define D 128
#define N_TILES ((N_NODES + 127) / 128)   // 391
#define ZERO_BLOCKS ((N_NODES * D / 4 + 255) / 256)   // 6250 (also covers x->fp16)
#define PACK_BLOCKS 16                                // 4096 threads

// ---------------------------------------------------------------------------
// Device scratch
// ---------------------------------------------------------------------------
__device__ float  g_h[(size_t)N_NODES * D];
__device__ __half g_xh[(size_t)N_NODES * D];   // fp16 mirror of x (gather payload)
// W packed in k-permuted bf16 m16n8k16 B-fragment order (see round 8)
__device__ float4 g_Wpack[16 * 8 * 32];

// ---------------------------------------------------------------------------
// bf16 helpers (plain sm_103 ISA)
// ---------------------------------------------------------------------------
__device__ __forceinline__ uint32_t pack_bf16x2(float lo, float hi) {
    uint32_t r;
    asm("cvt.rn.bf16x2.f32 %0, %1, %2;" : "=r"(r) : "f"(hi), "f"(lo));
    return r;
}
__device__ __forceinline__ float bf16x2_lo_f32(uint32_t v) {
    return __uint_as_float(v << 16);
}
__device__ __forceinline__ float bf16x2_hi_f32(uint32_t v) {
    return __uint_as_float(v & 0xffff0000u);
}

__device__ __forceinline__ void mma_bf16(float* acc,
                                         uint32_t a0, uint32_t a1,
                                         uint32_t a2, uint32_t a3,
                                         uint32_t b0, uint32_t b1) {
    asm volatile(
        "mma.sync.aligned.m16n8k16.row.col.f32.bf16.bf16.f32 "
        "{%0,%1,%2,%3}, {%4,%5,%6,%7}, {%8,%9}, {%0,%1,%2,%3};"
        : "+f"(acc[0]), "+f"(acc[1]), "+f"(acc[2]), "+f"(acc[3])
        : "r"(a0), "r"(a1), "r"(a2), "r"(a3), "r"(b0), "r"(b1));
}

// ---------------------------------------------------------------------------
// Kernel 1: fused init — zero g_h, convert x->fp16, pack W.
// Blocks [0, ZERO_BLOCKS): thread i zeroes g_h float4 i AND converts the
// matching 4 floats of x to g_xh. Blocks after: pack W.
// ---------------------------------------------------------------------------
__global__ void init_kernel(const float* __restrict__ x,
                            const float* __restrict__ W) {
    int bid = blockIdx.x;
    if (bid < ZERO_BLOCKS) {
        int i = bid * 256 + threadIdx.x;
        const int n4 = N_NODES * D / 4;
        if (i < n4) {
            reinterpret_cast<float4*>(g_h)[i] = make_float4(0.f, 0.f, 0.f, 0.f);
            float4 v = __ldg(reinterpret_cast<const float4*>(x) + i);
            __half2 h0 = __floats2half2_rn(v.x, v.y);
            __half2 h1 = __floats2half2_rn(v.z, v.w);
            uint2 packed = make_uint2(
                *reinterpret_cast<uint32_t*>(&h0),
                *reinterpret_cast<uint32_t*>(&h1));
            reinterpret_cast<uint2*>(g_xh)[i] = packed;
        }
        return;
    }
    int idx = (bid - ZERO_BLOCKS) * 256 + threadIdx.x;   // 0..4095
    if (idx >= 16 * 8 * 32) return;
    int lane = idx & 31;
    int kstep = (idx >> 5) & 7;
    int t = idx >> 8;
    int n = t * 8 + (lane >> 2);
    int k0 = kstep * 16 + (lane & 3) * 4;

    float w0 = __ldg(W + n * D + k0 + 0);
    float w1 = __ldg(W + n * D + k0 + 1);
    float w2 = __ldg(W + n * D + k0 + 2);
    float w3 = __ldg(W + n * D + k0 + 3);

    uint32_t bh0 = pack_bf16x2(w0, w1);
    uint32_t bh1 = pack_bf16x2(w2, w3);
    uint32_t bl0 = pack_bf16x2(w0 - bf16x2_lo_f32(bh0), w1 - bf16x2_hi_f32(bh0));
    uint32_t bl1 = pack_bf16x2(w2 - bf16x2_lo_f32(bh1), w3 - bf16x2_hi_f32(bh1));

    float4 v;
    v.x = __uint_as_float(bh0);
    v.y = __uint_as_float(bh1);
    v.z = __uint_as_float(bl0);
    v.w = __uint_as_float(bl1);
    g_Wpack[idx] = v;
}

// ---------------------------------------------------------------------------
// Kernel 2: edge scatter — one warp per edge.
// Gather fp16 (256B/edge, lane = LDG.64 of 4 halves), convert, then
// red.global.add.v4.f32 (512B/edge). 768B/edge total vs 1024B before.
// ---------------------------------------------------------------------------
__global__ void scatter_edges_kernel(const int* __restrict__ src,
                                     const int* __restrict__ dst,
                                     int n_edges) {
    int gw = (blockIdx.x * blockDim.x + threadIdx.x) >> 5;
    int lane = threadIdx.x & 31;
    if (gw >= n_edges) return;

    int s = __ldg(src + gw);
    int d = __ldg(dst + gw);

    uint2 p = __ldg(reinterpret_cast<const uint2*>(g_xh + (size_t)s * D) + lane);
    __half2 h0 = *reinterpret_cast<__half2*>(&p.x);
    __half2 h1 = *reinterpret_cast<__half2*>(&p.y);
    float2 f0 = __half22float2(h0);
    float2 f1 = __half22float2(h1);

    float* hp = g_h + (size_t)d * D + lane * 4;
    asm volatile("red.global.add.v4.f32 [%0], {%1, %2, %3, %4};"
                 :: "l"(hp), "f"(f0.x), "f"(f0.y), "f"(f1.x), "f"(f1.y)
                 : "memory");
}

// ---------------------------------------------------------------------------
// Kernel 3: out = h @ W^T + b via mma.sync bf16x3 (m16n8k16) — round-8 design.
// ---------------------------------------------------------------------------
#define SB_ELEMS (8 * 8 * 32)              // 2048 float4 = 32KB per column half

__global__ __launch_bounds__(256, 2) void gemm_mma_kernel(
    const float* __restrict__ bias,
    float* __restrict__ out) {

    extern __shared__ float4 sB[];         // [tt(8)][kstep(8)][lane(32)]

    const int tid = threadIdx.x;
    const int wid = tid >> 5;
    const int lane = tid & 31;
    const int q = lane & 3;
    const int half = blockIdx.y;

    {
        const float4* wsrc = g_Wpack + half * SB_ELEMS;
#pragma unroll
        for (int i = 0; i < SB_ELEMS / 256; i++)
            sB[i * 256 + tid] = __ldg(wsrc + i * 256 + tid);
    }

    const int r0 = blockIdx.x * 128 + wid * 16;
    const int rowA0 = r0 + (lane >> 2);
    const int rowA1 = rowA0 + 8;
    const int rc0 = rowA0 < N_NODES ? rowA0 : N_NODES - 1;
    const int rc1 = rowA1 < N_NODES ? rowA1 : N_NODES - 1;
    const float4* hp0 = reinterpret_cast<const float4*>(g_h + (size_t)rc0 * D) + q;
    const float4* hp1 = reinterpret_cast<const float4*>(g_h + (size_t)rc1 * D) + q;

    float acc[8][4];
#pragma unroll
    for (int t = 0; t < 8; t++)
#pragma unroll
        for (int c = 0; c < 4; c++) acc[t][c] = 0.f;

    __syncthreads();

#pragma unroll
    for (int kstep = 0; kstep < 8; kstep++) {
        float4 v0 = __ldg(hp0 + kstep * 4);
        float4 v1 = __ldg(hp1 + kstep * 4);

        uint32_t Ah0 = pack_bf16x2(v0.x, v0.y);
        uint32_t Ah1 = pack_bf16x2(v1.x, v1.y);
        uint32_t Ah2 = pack_bf16x2(v0.z, v0.w);
        uint32_t Ah3 = pack_bf16x2(v1.z, v1.w);
        uint32_t Al0 = pack_bf16x2(v0.x - bf16x2_lo_f32(Ah0), v0.y - bf16x2_hi_f32(Ah0));
        uint32_t Al1 = pack_bf16x2(v1.x - bf16x2_lo_f32(Ah1), v1.y - bf16x2_hi_f32(Ah1));
        uint32_t Al2 = pack_bf16x2(v0.z - bf16x2_lo_f32(Ah2), v0.w - bf16x2_hi_f32(Ah2));
        uint32_t Al3 = pack_bf16x2(v1.z - bf16x2_lo_f32(Ah3), v1.w - bf16x2_hi_f32(Ah3));

        const float4* wp = sB + kstep * 32 + lane;
#pragma unroll
        for (int t = 0; t < 8; t++) {
            float4 bf = wp[t * 256];
            uint32_t bh0 = __float_as_uint(bf.x);
            uint32_t bh1 = __float_as_uint(bf.y);
            uint32_t bl0 = __float_as_uint(bf.z);
            uint32_t bl1 = __float_as_uint(bf.w);
            mma_bf16(acc[t], Ah0, Ah1, Ah2, Ah3, bh0, bh1);
            mma_bf16(acc[t], Ah0, Ah1, Ah2, Ah3, bl0, bl1);
            mma_bf16(acc[t], Al0, Al1, Al2, Al3, bh0, bh1);
        }
    }

#pragma unroll
    for (int t = 0; t < 8; t++) {
        int col = half * 64 + t * 8 + q * 2;
        float b0 = __ldg(bias + col);
        float b1 = __ldg(bias + col + 1);
        if (rowA0 < N_NODES) {
            float2 v = make_float2(acc[t][0] + b0, acc[t][1] + b1);
            *reinterpret_cast<float2*>(out + (size_t)rowA0 * D + col) = v;
        }
        if (rowA1 < N_NODES) {
            float2 v = make_float2(acc[t][2] + b0, acc[t][3] + b1);
            *reinterpret_cast<float2*>(out + (size_t)rowA1 * D + col) = v;
        }
    }
}

// ---------------------------------------------------------------------------
// Launch: inputs in metadata order: x, src, dst, W, b
// ---------------------------------------------------------------------------
extern "C" void kernel_launch(void* const* d_in, const int* in_sizes, int n_in,
                              void* d_out, int out_size) {
    const float* x   = (const float*)d_in[0];
    const int*   src = (const int*)d_in[1];
    const int*   dst = (const int*)d_in[2];
    const float* W   = (const float*)d_in[3];
    const float* b   = (const float*)d_in[4];
    float* out = (float*)d_out;

    const int n_edges = in_sizes[1];

    // 1) fused init: zero g_h + x->fp16 + pack W
    init_kernel<<<ZERO_BLOCKS + PACK_BLOCKS, 256>>>(x, W);

    // 2) scatter-add edges (fp16 gather, fp32 atomics)
    {
        long long total_threads = (long long)n_edges * 32;
        int blocks = (int)((total_threads + 255) / 256);
        scatter_edges_kernel<<<blocks, 256>>>(src, dst, n_edges);
    }

    // 3) tensor-core GEMM + bias (bf16x3, m16n8k16)
    {
        static bool attr_set = false;
        if (!attr_set) {
            cudaFuncSetAttribute(gemm_mma_kernel,
                                 cudaFuncAttributeMaxDynamicSharedMemorySize,
                                 SB_ELEMS * sizeof(float4));
            attr_set = true;
        }
        dim3 grid(N_TILES, 2);
        gemm_mma_kernel<<<grid, 256, SB_ELEMS * sizeof(float4)>>>(b, out);
    }
}

// round 10
// speedup vs baseline: 1.6768x; 1.6768x over previous
#include <cuda_runtime.h>
#include <cuda_fp16.h>
#include <cstdint>

#define N_NODES 50000
#define D 128
#define N_TILES ((N_NODES + 127) / 128)   // 391
#define ZERO_BLOCKS ((N_NODES * D / 4 + 255) / 256)   // 6250
#define PACK_BLOCKS 16                                // 4096 threads
#define BUCKET 64

// ---------------------------------------------------------------------------
// Device scratch
// ---------------------------------------------------------------------------
__device__ float  g_h[(size_t)N_NODES * D];       // fp32 accumulator
__device__ __half g_xh[(size_t)N_NODES * D];      // fp16 mirror of x
__device__ int    g_cnt[N_NODES];                 // per-dst degree cursor
__device__ int    g_bucket[(size_t)N_NODES * BUCKET];  // src ids per dst
__device__ float4 g_Wpack[16 * 8 * 32];           // bf16 hi/lo B fragments

// ---------------------------------------------------------------------------
// helpers
// ---------------------------------------------------------------------------
__device__ __forceinline__ uint32_t pack_bf16x2(float lo, float hi) {
    uint32_t r;
    asm("cvt.rn.bf16x2.f32 %0, %1, %2;" : "=r"(r) : "f"(hi), "f"(lo));
    return r;
}
__device__ __forceinline__ float bf16x2_lo_f32(uint32_t v) {
    return __uint_as_float(v << 16);
}
__device__ __forceinline__ float bf16x2_hi_f32(uint32_t v) {
    return __uint_as_float(v & 0xffff0000u);
}

__device__ __forceinline__ void mma_bf16(float* acc,
                                         uint32_t a0, uint32_t a1,
                                         uint32_t a2, uint32_t a3,
                                         uint32_t b0, uint32_t b1) {
    asm volatile(
        "mma.sync.aligned.m16n8k16.row.col.f32.bf16.bf16.f32 "
        "{%0,%1,%2,%3}, {%4,%5,%6,%7}, {%8,%9}, {%0,%1,%2,%3};"
        : "+f"(acc[0]), "+f"(acc[1]), "+f"(acc[2]), "+f"(acc[3])
        : "r"(a0), "r"(a1), "r"(a2), "r"(a3), "r"(b0), "r"(b1));
}

__device__ __forceinline__ void red_add_v4(float* p, float a, float b, float c, float d) {
    asm volatile("red.global.add.v4.f32 [%0], {%1, %2, %3, %4};"
                 :: "l"(p), "f"(a), "f"(b), "f"(c), "f"(d) : "memory");
}

// ---------------------------------------------------------------------------
// Kernel 1: fused init — zero g_h + g_cnt, convert x->fp16, pack W.
// ---------------------------------------------------------------------------
__global__ void init_kernel(const float* __restrict__ x,
                            const float* __restrict__ W) {
    int bid = blockIdx.x;
    if (bid < ZERO_BLOCKS) {
        int i = bid * 256 + threadIdx.x;
        const int n4 = N_NODES * D / 4;
        if (i < n4) {
            reinterpret_cast<float4*>(g_h)[i] = make_float4(0.f, 0.f, 0.f, 0.f);
            float4 v = __ldg(reinterpret_cast<const float4*>(x) + i);
            __half2 h0 = __floats2half2_rn(v.x, v.y);
            __half2 h1 = __floats2half2_rn(v.z, v.w);
            uint2 packed = make_uint2(
                *reinterpret_cast<uint32_t*>(&h0),
                *reinterpret_cast<uint32_t*>(&h1));
            reinterpret_cast<uint2*>(g_xh)[i] = packed;
        }
        if (i < N_NODES / 4) reinterpret_cast<int4*>(g_cnt)[i] = make_int4(0, 0, 0, 0);
        return;
    }
    int idx = (bid - ZERO_BLOCKS) * 256 + threadIdx.x;   // 0..4095
    if (idx >= 16 * 8 * 32) return;
    int lane = idx & 31;
    int kstep = (idx >> 5) & 7;
    int t = idx >> 8;
    int n = t * 8 + (lane >> 2);
    int k0 = kstep * 16 + (lane & 3) * 4;

    float w0 = __ldg(W + n * D + k0 + 0);
    float w1 = __ldg(W + n * D + k0 + 1);
    float w2 = __ldg(W + n * D + k0 + 2);
    float w3 = __ldg(W + n * D + k0 + 3);

    uint32_t bh0 = pack_bf16x2(w0, w1);
    uint32_t bh1 = pack_bf16x2(w2, w3);
    uint32_t bl0 = pack_bf16x2(w0 - bf16x2_lo_f32(bh0), w1 - bf16x2_hi_f32(bh0));
    uint32_t bl1 = pack_bf16x2(w2 - bf16x2_lo_f32(bh1), w3 - bf16x2_hi_f32(bh1));

    float4 v;
    v.x = __uint_as_float(bh0);
    v.y = __uint_as_float(bh1);
    v.z = __uint_as_float(bl0);
    v.w = __uint_as_float(bl1);
    g_Wpack[idx] = v;
}

// ---------------------------------------------------------------------------
// Kernel 2: place — bucket src ids by dst (thread per edge, no scan).
// Rare overflow (deg > BUCKET) falls back to direct row atomics (correct
// for any input; never taken for Poisson(16) degrees).
// ---------------------------------------------------------------------------
__global__ void place_kernel(const int* __restrict__ src,
                             const int* __restrict__ dst,
                             int n_edges) {
    int e = blockIdx.x * blockDim.x + threadIdx.x;
    if (e >= n_edges) return;
    int s = __ldg(src + e);
    int d = __ldg(dst + e);
    int pos = atomicAdd(&g_cnt[d], 1);
    if (pos < BUCKET) {
        g_bucket[(size_t)d * BUCKET + pos] = s;
    } else {
        // fallback: add this row directly (32 x red.v4)
        const uint2* xr = reinterpret_cast<const uint2*>(g_xh + (size_t)s * D);
        float* hp = g_h + (size_t)d * D;
        for (int i = 0; i < 32; i++) {
            uint2 p = __ldg(xr + i);
            __half2 h0 = *reinterpret_cast<__half2*>(&p.x);
            __half2 h1 = *reinterpret_cast<__half2*>(&p.y);
            float2 f0 = __half22float2(h0);
            float2 f1 = __half22float2(h1);
            red_add_v4(hp + i * 4, f0.x, f0.y, f1.x, f1.y);
        }
    }
}

// ---------------------------------------------------------------------------
// Kernel 3: gather — one warp per node. Broadcast bucket ids via shfl,
// gather fp16 rows, accumulate fp32 in registers, ONE red.v4 per lane.
// (16x fewer atomic lane-ops than edge-scatter.)
// ---------------------------------------------------------------------------
__global__ void gather_kernel() {
    int gw = (blockIdx.x * blockDim.x + threadIdx.x) >> 5;
    int lane = threadIdx.x & 31;
    if (gw >= N_NODES) return;

    int deg = g_cnt[gw];
    int n = min(deg, BUCKET);
    if (n == 0) return;

    const int* bp = g_bucket + (size_t)gw * BUCKET;
    int s0 = (lane < n) ? __ldg(bp + lane) : 0;
    int s1 = (lane + 32 < n) ? __ldg(bp + lane + 32) : 0;

    float4 acc = make_float4(0.f, 0.f, 0.f, 0.f);

    int full = min(n, 32);
    int j = 0;
    // 2-way unroll for MLP
    for (; j + 1 < full; j += 2) {
        int sa = __shfl_sync(0xffffffffu, s0, j);
        int sb = __shfl_sync(0xffffffffu, s0, j + 1);
        uint2 pa = __ldg(reinterpret_cast<const uint2*>(g_xh + (size_t)sa * D) + lane);
        uint2 pb = __ldg(reinterpret_cast<const uint2*>(g_xh + (size_t)sb * D) + lane);
        __half2 a0 = *reinterpret_cast<__half2*>(&pa.x);
        __half2 a1 = *reinterpret_cast<__half2*>(&pa.y);
        __half2 b0 = *reinterpret_cast<__half2*>(&pb.x);
        __half2 b1 = *reinterpret_cast<__half2*>(&pb.y);
        float2 fa0 = __half22float2(a0), fa1 = __half22float2(a1);
        float2 fb0 = __half22float2(b0), fb1 = __half22float2(b1);
        acc.x += fa0.x + fb0.x;
        acc.y += fa0.y + fb0.y;
        acc.z += fa1.x + fb1.x;
        acc.w += fa1.y + fb1.y;
    }
    for (; j < full; j++) {
        int sa = __shfl_sync(0xffffffffu, s0, j);
        uint2 pa = __ldg(reinterpret_cast<const uint2*>(g_xh + (size_t)sa * D) + lane);
        __half2 a0 = *reinterpret_cast<__half2*>(&pa.x);
        __half2 a1 = *reinterpret_cast<__half2*>(&pa.y);
        float2 fa0 = __half22float2(a0), fa1 = __half22float2(a1);
        acc.x += fa0.x; acc.y += fa0.y; acc.z += fa1.x; acc.w += fa1.y;
    }
    for (j = 32; j < n; j++) {
        int sa = __shfl_sync(0xffffffffu, s1, j - 32);
        uint2 pa = __ldg(reinterpret_cast<const uint2*>(g_xh + (size_t)sa * D) + lane);
        __half2 a0 = *reinterpret_cast<__half2*>(&pa.x);
        __half2 a1 = *reinterpret_cast<__half2*>(&pa.y);
        float2 fa0 = __half22float2(a0), fa1 = __half22float2(a1);
        acc.x += fa0.x; acc.y += fa0.y; acc.z += fa1.x; acc.w += fa1.y;
    }

    // combine with any fallback contributions already in g_h
    red_add_v4(g_h + (size_t)gw * D + lane * 4, acc.x, acc.y, acc.z, acc.w);
}

// ---------------------------------------------------------------------------
// Kernel 4: out = h @ W^T + b via mma.sync bf16x3 (m16n8k16) — round-8 design.
// ---------------------------------------------------------------------------
#define SB_ELEMS (8 * 8 * 32)              // 2048 float4 = 32KB per column half

__global__ __launch_bounds__(256, 2) void gemm_mma_kernel(
    const float* __restrict__ bias,
    float* __restrict__ out) {

    extern __shared__ float4 sB[];

    const int tid = threadIdx.x;
    const int wid = tid >> 5;
    const int lane = tid & 31;
    const int q = lane & 3;
    const int half = blockIdx.y;

    {
        const float4* wsrc = g_Wpack + half * SB_ELEMS;
#pragma unroll
        for (int i = 0; i < SB_ELEMS / 256; i++)
            sB[i * 256 + tid] = __ldg(wsrc + i * 256 + tid);
    }

    const int r0 = blockIdx.x * 128 + wid * 16;
    const int rowA0 = r0 + (lane >> 2);
    const int rowA1 = rowA0 + 8;
    const int rc0 = rowA0 < N_NODES ? rowA0 : N_NODES - 1;
    const int rc1 = rowA1 < N_NODES ? rowA1 : N_NODES - 1;
    const float4* hp0 = reinterpret_cast<const float4*>(g_h + (size_t)rc0 * D) + q;
    const float4* hp1 = reinterpret_cast<const float4*>(g_h + (size_t)rc1 * D) + q;

    float acc[8][4];
#pragma unroll
    for (int t = 0; t < 8; t++)
#pragma unroll
        for (int c = 0; c < 4; c++) acc[t][c] = 0.f;

    __syncthreads();

#pragma unroll
    for (int kstep = 0; kstep < 8; kstep++) {
        float4 v0 = __ldg(hp0 + kstep * 4);
        float4 v1 = __ldg(hp1 + kstep * 4);

        uint32_t Ah0 = pack_bf16x2(v0.x, v0.y);
        uint32_t Ah1 = pack_bf16x2(v1.x, v1.y);
        uint32_t Ah2 = pack_bf16x2(v0.z, v0.w);
        uint32_t Ah3 = pack_bf16x2(v1.z, v1.w);
        uint32_t Al0 = pack_bf16x2(v0.x - bf16x2_lo_f32(Ah0), v0.y - bf16x2_hi_f32(Ah0));
        uint32_t Al1 = pack_bf16x2(v1.x - bf16x2_lo_f32(Ah1), v1.y - bf16x2_hi_f32(Ah1));
        uint32_t Al2 = pack_bf16x2(v0.z - bf16x2_lo_f32(Ah2), v0.w - bf16x2_hi_f32(Ah2));
        uint32_t Al3 = pack_bf16x2(v1.z - bf16x2_lo_f32(Ah3), v1.w - bf16x2_hi_f32(Ah3));

        const float4* wp = sB + kstep * 32 + lane;
#pragma unroll
        for (int t = 0; t < 8; t++) {
            float4 bf = wp[t * 256];
            uint32_t bh0 = __float_as_uint(bf.x);
            uint32_t bh1 = __float_as_uint(bf.y);
            uint32_t bl0 = __float_as_uint(bf.z);
            uint32_t bl1 = __float_as_uint(bf.w);
            mma_bf16(acc[t], Ah0, Ah1, Ah2, Ah3, bh0, bh1);
            mma_bf16(acc[t], Ah0, Ah1, Ah2, Ah3, bl0, bl1);
            mma_bf16(acc[t], Al0, Al1, Al2, Al3, bh0, bh1);
        }
    }

#pragma unroll
    for (int t = 0; t < 8; t++) {
        int col = half * 64 + t * 8 + q * 2;
        float b0 = __ldg(bias + col);
        float b1 = __ldg(bias + col + 1);
        if (rowA0 < N_NODES) {
            float2 v = make_float2(acc[t][0] + b0, acc[t][1] + b1);
            *reinterpret_cast<float2*>(out + (size_t)rowA0 * D + col) = v;
        }
        if (rowA1 < N_NODES) {
            float2 v = make_float2(acc[t][2] + b0, acc[t][3] + b1);
            *reinterpret_cast<float2*>(out + (size_t)rowA1 * D + col) = v;
        }
    }
}

// ---------------------------------------------------------------------------
// Launch: inputs in metadata order: x, src, dst, W, b
// ---------------------------------------------------------------------------
extern "C" void kernel_launch(void* const* d_in, const int* in_sizes, int n_in,
                              void* d_out, int out_size) {
    const float* x   = (const float*)d_in[0];
    const int*   src = (const int*)d_in[1];
    const int*   dst = (const int*)d_in[2];
    const float* W   = (const float*)d_in[3];
    const float* b   = (const float*)d_in[4];
    float* out = (float*)d_out;

    const int n_edges = in_sizes[1];

    // 1) fused init: zero g_h + g_cnt, x->fp16, pack W
    init_kernel<<<ZERO_BLOCKS + PACK_BLOCKS, 256>>>(x, W);

    // 2) place: bucket src ids by dst (no scan)
    place_kernel<<<(n_edges + 255) / 256, 256>>>(src, dst, n_edges);

    // 3) gather: warp per node, fp16 gather, one row-atomic per node
    {
        long long total_threads = (long long)N_NODES * 32;
        int blocks = (int)((total_threads + 255) / 256);
        gather_kernel<<<blocks, 256>>>();
    }

    // 4) tensor-core GEMM + bias (bf16x3, m16n8k16)
    {
        static bool attr_set = false;
        if (!attr_set) {
            cudaFuncSetAttribute(gemm_mma_kernel,
                                 cudaFuncAttributeMaxDynamicSharedMemorySize,
                                 SB_ELEMS * sizeof(float4));
            attr_set = true;
        }
        dim3 grid(N_TILES, 2);
        gemm_mma_kernel<<<grid, 256, SB_ELEMS * sizeof(float4)>>>(b, out);
    }
}

// round 11
// speedup vs baseline: 1.7742x; 1.0581x over previous
#include <cuda_runtime.h>
#include <cuda_fp16.h>
#include <cstdint>

#define N_NODES 50000
#define D 128
#define N_TILES ((N_NODES + 127) / 128)   // 391
#define CVT_BLOCKS ((N_NODES * D / 4 + 255) / 256)    // 6250
#define PACK_BLOCKS 16                                // 4096 threads
#define BUCKET 64
#define MAX_OFLOW 800000

// ---------------------------------------------------------------------------
// Device scratch
// ---------------------------------------------------------------------------
__device__ __half g_xh[(size_t)N_NODES * D];      // fp16 mirror of x
__device__ __half g_hf[(size_t)N_NODES * D];      // fp16 aggregated features
__device__ int    g_cnt[N_NODES];                 // per-dst degree cursor
__device__ int    g_bucket[(size_t)N_NODES * BUCKET];
__device__ int    g_oflow_cnt;
__device__ int    g_oflow_src[MAX_OFLOW];
__device__ int    g_oflow_dst[MAX_OFLOW];
__device__ float4 g_Wpack[16 * 8 * 32];           // fp16 hi/lo B fragments

// ---------------------------------------------------------------------------
// helpers
// ---------------------------------------------------------------------------
__device__ __forceinline__ void mma_f16(float* acc,
                                        uint32_t a0, uint32_t a1,
                                        uint32_t a2, uint32_t a3,
                                        uint32_t b0, uint32_t b1) {
    asm volatile(
        "mma.sync.aligned.m16n8k16.row.col.f32.f16.f16.f32 "
        "{%0,%1,%2,%3}, {%4,%5,%6,%7}, {%8,%9}, {%0,%1,%2,%3};"
        : "+f"(acc[0]), "+f"(acc[1]), "+f"(acc[2]), "+f"(acc[3])
        : "r"(a0), "r"(a1), "r"(a2), "r"(a3), "r"(b0), "r"(b1));
}

__device__ __forceinline__ uint32_t pack_h2(float lo, float hi) {
    __half2 h = __floats2half2_rn(lo, hi);
    return *reinterpret_cast<uint32_t*>(&h);
}

// ---------------------------------------------------------------------------
// Kernel 1: fused init — x->fp16, zero g_cnt + oflow counter, pack W (fp16 hi/lo).
// ---------------------------------------------------------------------------
__global__ void init_kernel(const float* __restrict__ x,
                            const float* __restrict__ W) {
    int bid = blockIdx.x;
    if (bid == 0 && threadIdx.x == 0) g_oflow_cnt = 0;
    if (bid < CVT_BLOCKS) {
        int i = bid * 256 + threadIdx.x;
        const int n4 = N_NODES * D / 4;
        if (i < n4) {
            float4 v = __ldg(reinterpret_cast<const float4*>(x) + i);
            uint2 packed = make_uint2(pack_h2(v.x, v.y), pack_h2(v.z, v.w));
            reinterpret_cast<uint2*>(g_xh)[i] = packed;
        }
        if (i < N_NODES / 4) reinterpret_cast<int4*>(g_cnt)[i] = make_int4(0, 0, 0, 0);
        return;
    }
    int idx = (bid - CVT_BLOCKS) * 256 + threadIdx.x;   // 0..4095
    if (idx >= 16 * 8 * 32) return;
    int lane = idx & 31;
    int kstep = (idx >> 5) & 7;
    int t = idx >> 8;
    int n = t * 8 + (lane >> 2);
    int k0 = kstep * 16 + (lane & 3) * 4;

    float w0 = __ldg(W + n * D + k0 + 0);
    float w1 = __ldg(W + n * D + k0 + 1);
    float w2 = __ldg(W + n * D + k0 + 2);
    float w3 = __ldg(W + n * D + k0 + 3);

    __half wh0 = __float2half_rn(w0), wh1 = __float2half_rn(w1);
    __half wh2 = __float2half_rn(w2), wh3 = __float2half_rn(w3);
    float r0 = w0 - __half2float(wh0), r1 = w1 - __half2float(wh1);
    float r2 = w2 - __half2float(wh2), r3 = w3 - __half2float(wh3);

    float4 v;
    v.x = __uint_as_float(pack_h2(__half2float(wh0), __half2float(wh1)));
    v.y = __uint_as_float(pack_h2(__half2float(wh2), __half2float(wh3)));
    v.z = __uint_as_float(pack_h2(r0, r1));
    v.w = __uint_as_float(pack_h2(r2, r3));
    g_Wpack[idx] = v;
}

// ---------------------------------------------------------------------------
// Kernel 2: place — bucket src ids by dst; overflow -> list (normally empty).
// ---------------------------------------------------------------------------
__global__ void place_kernel(const int* __restrict__ src,
                             const int* __restrict__ dst,
                             int n_edges) {
    int e = blockIdx.x * blockDim.x + threadIdx.x;
    if (e >= n_edges) return;
    int s = __ldg(src + e);
    int d = __ldg(dst + e);
    int pos = atomicAdd(&g_cnt[d], 1);
    if (pos < BUCKET) {
        g_bucket[(size_t)d * BUCKET + pos] = s;
    } else {
        int o = atomicAdd(&g_oflow_cnt, 1);
        if (o < MAX_OFLOW) { g_oflow_src[o] = s; g_oflow_dst[o] = d; }
    }
}

// ---------------------------------------------------------------------------
// Kernel 3: gather — one warp per node: shfl-broadcast bucket ids, gather
// fp16 rows, fp32 register accumulate, store the row as fp16 (plain store).
// ---------------------------------------------------------------------------
__global__ void gather_kernel() {
    int gw = (blockIdx.x * blockDim.x + threadIdx.x) >> 5;
    int lane = threadIdx.x & 31;
    if (gw >= N_NODES) return;

    int deg = g_cnt[gw];
    int n = min(deg, BUCKET);

    float4 acc = make_float4(0.f, 0.f, 0.f, 0.f);

    if (n > 0) {
        const int* bp = g_bucket + (size_t)gw * BUCKET;
        int s0 = (lane < n) ? __ldg(bp + lane) : 0;
        int s1 = (lane + 32 < n) ? __ldg(bp + lane + 32) : 0;

        int full = min(n, 32);
        int j = 0;
        for (; j + 1 < full; j += 2) {
            int sa = __shfl_sync(0xffffffffu, s0, j);
            int sb = __shfl_sync(0xffffffffu, s0, j + 1);
            uint2 pa = __ldg(reinterpret_cast<const uint2*>(g_xh + (size_t)sa * D) + lane);
            uint2 pb = __ldg(reinterpret_cast<const uint2*>(g_xh + (size_t)sb * D) + lane);
            float2 fa0 = __half22float2(*reinterpret_cast<__half2*>(&pa.x));
            float2 fa1 = __half22float2(*reinterpret_cast<__half2*>(&pa.y));
            float2 fb0 = __half22float2(*reinterpret_cast<__half2*>(&pb.x));
            float2 fb1 = __half22float2(*reinterpret_cast<__half2*>(&pb.y));
            acc.x += fa0.x + fb0.x;
            acc.y += fa0.y + fb0.y;
            acc.z += fa1.x + fb1.x;
            acc.w += fa1.y + fb1.y;
        }
        for (; j < full; j++) {
            int sa = __shfl_sync(0xffffffffu, s0, j);
            uint2 pa = __ldg(reinterpret_cast<const uint2*>(g_xh + (size_t)sa * D) + lane);
            float2 fa0 = __half22float2(*reinterpret_cast<__half2*>(&pa.x));
            float2 fa1 = __half22float2(*reinterpret_cast<__half2*>(&pa.y));
            acc.x += fa0.x; acc.y += fa0.y; acc.z += fa1.x; acc.w += fa1.y;
        }
        for (j = 32; j < n; j++) {
            int sa = __shfl_sync(0xffffffffu, s1, j - 32);
            uint2 pa = __ldg(reinterpret_cast<const uint2*>(g_xh + (size_t)sa * D) + lane);
            float2 fa0 = __half22float2(*reinterpret_cast<__half2*>(&pa.x));
            float2 fa1 = __half22float2(*reinterpret_cast<__half2*>(&pa.y));
            acc.x += fa0.x; acc.y += fa0.y; acc.z += fa1.x; acc.w += fa1.y;
        }
    }

    uint2 packed = make_uint2(pack_h2(acc.x, acc.y), pack_h2(acc.z, acc.w));
    reinterpret_cast<uint2*>(g_hf + (size_t)gw * D)[lane] = packed;
}

// ---------------------------------------------------------------------------
// Kernel 4: fixup — process overflow edges (normally zero) with f16x2 atomics.
// One warp per overflow edge, strided.
// ---------------------------------------------------------------------------
__global__ void fixup_kernel() {
    int m = g_oflow_cnt;
    if (m == 0) return;
    if (m > MAX_OFLOW) m = MAX_OFLOW;
    int gw = (blockIdx.x * blockDim.x + threadIdx.x) >> 5;
    int lane = threadIdx.x & 31;
    int nw = (gridDim.x * blockDim.x) >> 5;
    for (int e = gw; e < m; e += nw) {
        int s = g_oflow_src[e];
        int d = g_oflow_dst[e];
        uint2 p = __ldg(reinterpret_cast<const uint2*>(g_xh + (size_t)s * D) + lane);
        __half* hp = g_hf + (size_t)d * D + lane * 4;
        asm volatile("red.global.add.noftz.f16x2 [%0], %1;" :: "l"(hp), "r"(p.x) : "memory");
        asm volatile("red.global.add.noftz.f16x2 [%0], %1;" :: "l"(hp + 2), "r"(p.y) : "memory");
    }
}

// ---------------------------------------------------------------------------
// Kernel 5: out = h @ W^T + b via 2-term fp16 mma (A exact in fp16).
// One warp per 16 rows x 64 cols; blockIdx.y = column half.
// A: 2 x LDG.64 per thread per kstep, directly usable as mma fragments.
// B: fp16 hi/lo staged once per block (32KB smem).
// Per warp: 128 mma + 64 lds + 16 ldg, NO conversions.
// ---------------------------------------------------------------------------
#define SB_ELEMS (8 * 8 * 32)              // 2048 float4 = 32KB per column half

__global__ __launch_bounds__(256, 3) void gemm_mma_kernel(
    const float* __restrict__ bias,
    float* __restrict__ out) {

    extern __shared__ float4 sB[];

    const int tid = threadIdx.x;
    const int wid = tid >> 5;
    const int lane = tid & 31;
    const int q = lane & 3;
    const int half = blockIdx.y;

    {
        const float4* wsrc = g_Wpack + half * SB_ELEMS;
#pragma unroll
        for (int i = 0; i < SB_ELEMS / 256; i++)
            sB[i * 256 + tid] = __ldg(wsrc + i * 256 + tid);
    }

    const int r0 = blockIdx.x * 128 + wid * 16;
    const int rowA0 = r0 + (lane >> 2);
    const int rowA1 = rowA0 + 8;
    const int rc0 = rowA0 < N_NODES ? rowA0 : N_NODES - 1;
    const int rc1 = rowA1 < N_NODES ? rowA1 : N_NODES - 1;
    // uint2 = 4 halves; thread's k-chunk = q -> halves 4q..4q+3
    const uint2* hp0 = reinterpret_cast<const uint2*>(g_hf + (size_t)rc0 * D) + q;
    const uint2* hp1 = reinterpret_cast<const uint2*>(g_hf + (size_t)rc1 * D) + q;

    float acc[8][4];
#pragma unroll
    for (int t = 0; t < 8; t++)
#pragma unroll
        for (int c = 0; c < 4; c++) acc[t][c] = 0.f;

    __syncthreads();

#pragma unroll
    for (int kstep = 0; kstep < 8; kstep++) {
        // physical k = kstep*16 + q*4 + {0..3}; one uint2 per row
        uint2 p0 = __ldg(hp0 + kstep * 4);
        uint2 p1 = __ldg(hp1 + kstep * 4);
        uint32_t A0 = p0.x, A2 = p0.y;   // row r:  k{0,1}, k{2,3}
        uint32_t A1 = p1.x, A3 = p1.y;   // row r+8

        const float4* wp = sB + kstep * 32 + lane;
#pragma unroll
        for (int t = 0; t < 8; t++) {
            float4 bf = wp[t * 256];
            uint32_t bh0 = __float_as_uint(bf.x);
            uint32_t bh1 = __float_as_uint(bf.y);
            uint32_t bl0 = __float_as_uint(bf.z);
            uint32_t bl1 = __float_as_uint(bf.w);
            mma_f16(acc[t], A0, A1, A2, A3, bh0, bh1);   // A*Wh
            mma_f16(acc[t], A0, A1, A2, A3, bl0, bl1);   // A*Wl
        }
    }

#pragma unroll
    for (int t = 0; t < 8; t++) {
        int col = half * 64 + t * 8 + q * 2;
        float b0 = __ldg(bias + col);
        float b1 = __ldg(bias + col + 1);
        if (rowA0 < N_NODES) {
            float2 v = make_float2(acc[t][0] + b0, acc[t][1] + b1);
            *reinterpret_cast<float2*>(out + (size_t)rowA0 * D + col) = v;
        }
        if (rowA1 < N_NODES) {
            float2 v = make_float2(acc[t][2] + b0, acc[t][3] + b1);
            *reinterpret_cast<float2*>(out + (size_t)rowA1 * D + col) = v;
        }
    }
}

// ---------------------------------------------------------------------------
// Launch: inputs in metadata order: x, src, dst, W, b
// ---------------------------------------------------------------------------
extern "C" void kernel_launch(void* const* d_in, const int* in_sizes, int n_in,
                              void* d_out, int out_size) {
    const float* x   = (const float*)d_in[0];
    const int*   src = (const int*)d_in[1];
    const int*   dst = (const int*)d_in[2];
    const float* W   = (const float*)d_in[3];
    const float* b   = (const float*)d_in[4];
    float* out = (float*)d_out;

    const int n_edges = in_sizes[1];

    // 1) fused init: x->fp16, zero counters, pack W (fp16 hi/lo)
    init_kernel<<<CVT_BLOCKS + PACK_BLOCKS, 256>>>(x, W);

    // 2) place: bucket src ids by dst
    place_kernel<<<(n_edges + 255) / 256, 256>>>(src, dst, n_edges);

    // 3) gather: warp per node, fp32 accumulate, fp16 store
    {
        long long total_threads = (long long)N_NODES * 32;
        int blocks = (int)((total_threads + 255) / 256);
        gather_kernel<<<blocks, 256>>>();
    }

    // 4) fixup overflow edges (normally a no-op)
    fixup_kernel<<<64, 256>>>();

    // 5) 2-term fp16 tensor-core GEMM + bias
    {
        static bool attr_set = false;
        if (!attr_set) {
            cudaFuncSetAttribute(gemm_mma_kernel,
                                 cudaFuncAttributeMaxDynamicSharedMemorySize,
                                 SB_ELEMS * sizeof(float4));
            attr_set = true;
        }
        dim3 grid(N_TILES, 2);
        gemm_mma_kernel<<<grid, 256, SB_ELEMS * sizeof(float4)>>>(b, out);
    }
}